// round 1
// baseline (speedup 1.0000x reference)
#include <cuda_runtime.h>

// 3x3 stride-1 pad-1 single-channel conv, weight scaled by outer(kx,kx),
// kx = [den[0], 1, den[0]].
// x: (B=16, 1, H=2048, W=2048) fp32. out: same shape fp32.
// Memory-bound: 256MB in + 256MB out. Shared-memory tiling ensures exactly
// one HBM read per input element.

#define TW 128          // output tile width (32 float4 lanes)
#define TH 16           // output tile height
#define HALO_W 130      // TW + 2
#define SW 132          // smem row stride in floats (130 padded to mult of 4)
#define SH 18           // TH + 2

__global__ __launch_bounds__(256, 8)
void conv3x3_kernel(const float* __restrict__ x,
                    const float* __restrict__ w,
                    const float* __restrict__ den,
                    float* __restrict__ out,
                    int H, int W)
{
    __shared__ float tile[SH * SW];

    const int tid = threadIdx.x;
    const int bx = blockIdx.x;   // tile col
    const int by = blockIdx.y;   // tile row
    const int b  = blockIdx.z;   // batch

    const size_t img = (size_t)H * W;
    const float* __restrict__ xb = x + (size_t)b * img;
    float* __restrict__ ob = out + (size_t)b * img;

    const int gx0 = bx * TW - 1;
    const int gy0 = by * TH - 1;

    // ---- cooperative halo load: SH x HALO_W floats, coalesced scalar loads ----
    #pragma unroll
    for (int i = tid; i < SH * HALO_W; i += 256) {
        const int r = i / HALO_W;
        const int c = i - r * HALO_W;
        const int gy = gy0 + r;
        const int gx = gx0 + c;
        float v = 0.0f;
        if ((unsigned)gy < (unsigned)H && (unsigned)gx < (unsigned)W)
            v = __ldg(&xb[(size_t)gy * W + gx]);
        tile[r * SW + c] = v;
    }

    // ---- effective weights (broadcast loads, L1 hit) ----
    const float d = den[0];
    const float kv0 = d, kv1 = 1.0f, kv2 = d;
    float k[9];
    {
        const float kvi[3] = {kv0, kv1, kv2};
        #pragma unroll
        for (int i = 0; i < 3; i++)
            #pragma unroll
            for (int j = 0; j < 3; j++)
                k[i * 3 + j] = __ldg(&w[i * 3 + j]) * kvi[i] * kvi[j];
    }

    __syncthreads();

    const int tx = tid & 31;   // float4 lane: output cols tx*4 .. tx*4+3
    const int ty = tid >> 5;   // 0..7, handles rows ty and ty+8
    const int lc = tx * 4;

    #pragma unroll
    for (int rr = 0; rr < 2; rr++) {
        const int lr = ty + rr * 8;          // local output row 0..15
        const int gy = by * TH + lr;

        float a0 = 0.f, a1 = 0.f, a2 = 0.f, a3 = 0.f;
        #pragma unroll
        for (int i = 0; i < 3; i++) {
            // rows lr..lr+2 of smem, cols lc..lc+5 — two aligned float4 LDS
            const float4 A = *reinterpret_cast<const float4*>(&tile[(lr + i) * SW + lc]);
            const float4 B = *reinterpret_cast<const float4*>(&tile[(lr + i) * SW + lc + 4]);
            const float s0 = A.x, s1 = A.y, s2 = A.z, s3 = A.w, s4 = B.x, s5 = B.y;
            const float w0 = k[i * 3 + 0], w1 = k[i * 3 + 1], w2 = k[i * 3 + 2];
            a0 = fmaf(w0, s0, fmaf(w1, s1, fmaf(w2, s2, a0)));
            a1 = fmaf(w0, s1, fmaf(w1, s2, fmaf(w2, s3, a1)));
            a2 = fmaf(w0, s2, fmaf(w1, s3, fmaf(w2, s4, a2)));
            a3 = fmaf(w0, s3, fmaf(w1, s4, fmaf(w2, s5, a3)));
        }
        float4 o = make_float4(a0, a1, a2, a3);
        *reinterpret_cast<float4*>(&ob[(size_t)gy * W + bx * TW + lc]) = o;
    }
}

extern "C" void kernel_launch(void* const* d_in, const int* in_sizes, int n_in,
                              void* d_out, int out_size)
{
    const float* x   = (const float*)d_in[0];   // (16,1,2048,2048) fp32
    const float* w   = (const float*)d_in[1];   // (1,1,3,3) fp32
    const float* den = (const float*)d_in[2];   // (1,) fp32
    float* out = (float*)d_out;

    const int B = 16, H = 2048, W = 2048;
    (void)in_sizes; (void)n_in; (void)out_size;

    dim3 grid(W / TW, H / TH, B);   // 16 x 128 x 16 = 32768 CTAs
    dim3 block(256);
    conv3x3_kernel<<<grid, block>>>(x, w, den, out, H, W);
}

// round 2
// speedup vs baseline: 1.0143x; 1.0143x over previous
#include <cuda_runtime.h>

// 3x3 stride-1 pad-1 conv, 1 channel, weight scaled by outer(kx,kx), kx=[den,1,den].
// x: (16,1,2048,2048) fp32 -> out same shape.
// Register-rolling strips: each warp computes a 128-col x 16-row strip.
// Per input row: 1 LDG.128/lane + 2 SHFL for neighbors (+1 scalar LDG on edge lanes).
// No shared memory, no syncthreads, no integer division.

#define RH 16        // output rows per warp
#define WCOLS 128    // columns per warp (32 lanes x float4)
#define WARPS 8      // warps per block

__global__ __launch_bounds__(256)
void conv3x3_roll(const float* __restrict__ x,
                  const float* __restrict__ w,
                  const float* __restrict__ den,
                  float* __restrict__ out,
                  int H, int W)
{
    const int lane = threadIdx.x & 31;
    const int wid  = threadIdx.x >> 5;
    const int b    = blockIdx.z;
    const int colbase = blockIdx.x * WCOLS;
    const int row0 = (blockIdx.y * WARPS + wid) * RH;  // first output row of this warp

    const size_t img = (size_t)H * W;
    const float* __restrict__ xb = x + (size_t)b * img;
    float*       __restrict__ ob = out + (size_t)b * img;

    // effective 3x3 weights (broadcast loads)
    const float d = den[0];
    const float kv[3] = {d, 1.0f, d};
    float k[9];
    #pragma unroll
    for (int i = 0; i < 3; i++)
        #pragma unroll
        for (int j = 0; j < 3; j++)
            k[i * 3 + j] = __ldg(&w[i * 3 + j]) * kv[i] * kv[j];

    const bool leftOK  = (colbase - 1) >= 0;
    const bool rightOK = (colbase + WCOLS) < W;
    const float* pcol = xb + colbase;   // column base, row offset added per load

    float r0[6], r1[6], r2[6];

    // load one padded input row into s[0..5] = cols [4*lane-1 .. 4*lane+4]
    auto load_row = [&](int gy, float* s) {
        if ((unsigned)gy < (unsigned)H) {           // warp-uniform predicate
            const float* p = pcol + (size_t)gy * W;
            const float4 v = *reinterpret_cast<const float4*>(p + 4 * lane);
            float lf = __shfl_up_sync(0xffffffffu, v.w, 1);
            float rt = __shfl_down_sync(0xffffffffu, v.x, 1);
            if (lane == 0)  lf = leftOK  ? __ldg(p - 1)      : 0.0f;
            if (lane == 31) rt = rightOK ? __ldg(p + WCOLS)  : 0.0f;
            s[0] = lf; s[1] = v.x; s[2] = v.y; s[3] = v.z; s[4] = v.w; s[5] = rt;
        } else {
            #pragma unroll
            for (int i = 0; i < 6; i++) s[i] = 0.0f;
        }
    };

    load_row(row0 - 1, r0);
    load_row(row0,     r1);

    float* ro = ob + (size_t)row0 * W + colbase + 4 * lane;

    #pragma unroll
    for (int rr = 0; rr < RH; rr++) {
        load_row(row0 + rr + 1, r2);

        float a0 = 0.f, a1 = 0.f, a2 = 0.f, a3 = 0.f;
        #pragma unroll
        for (int i = 0; i < 3; i++) {
            const float* s = (i == 0) ? r0 : (i == 1) ? r1 : r2;
            const float w0 = k[3 * i], w1 = k[3 * i + 1], w2 = k[3 * i + 2];
            a0 = fmaf(w0, s[0], fmaf(w1, s[1], fmaf(w2, s[2], a0)));
            a1 = fmaf(w0, s[1], fmaf(w1, s[2], fmaf(w2, s[3], a1)));
            a2 = fmaf(w0, s[2], fmaf(w1, s[3], fmaf(w2, s[4], a2)));
            a3 = fmaf(w0, s[3], fmaf(w1, s[4], fmaf(w2, s[5], a3)));
        }

        *reinterpret_cast<float4*>(ro) = make_float4(a0, a1, a2, a3);
        ro += W;

        // rotate window (register renaming after full unroll; no real copies)
        #pragma unroll
        for (int i = 0; i < 6; i++) { r0[i] = r1[i]; r1[i] = r2[i]; }
    }
}

extern "C" void kernel_launch(void* const* d_in, const int* in_sizes, int n_in,
                              void* d_out, int out_size)
{
    const float* x   = (const float*)d_in[0];   // (16,1,2048,2048) fp32
    const float* w   = (const float*)d_in[1];   // (1,1,3,3) fp32
    const float* den = (const float*)d_in[2];   // (1,) fp32
    float* out = (float*)d_out;

    const int B = 16, H = 2048, W = 2048;
    (void)in_sizes; (void)n_in; (void)out_size;

    dim3 grid(W / WCOLS, H / (WARPS * RH), B);  // 16 x 16 x 16 = 4096 CTAs
    dim3 block(256);
    conv3x3_roll<<<grid, block>>>(x, w, den, out, H, W);
}

// round 3
// speedup vs baseline: 1.0674x; 1.0524x over previous
#include <cuda_runtime.h>

// 3x3 stride-1 pad-1 conv, 1 channel, weight = w * outer(kx,kx), kx=[den,1,den].
// x: (16,1,2048,2048) fp32 -> out same shape.
// Register-rolling warp strips (128 cols x 16 rows) with a 4-deep unconditional
// load queue on the interior path to maximize memory-level parallelism.

#define RH 16        // output rows per warp strip
#define WCOLS 128    // columns per warp (32 lanes x float4)
#define WARPS 8      // warps per block

__global__ __launch_bounds__(256)
void conv3x3_pf(const float* __restrict__ x,
                const float* __restrict__ w,
                const float* __restrict__ den,
                float* __restrict__ out,
                int H, int W)
{
    const int lane = threadIdx.x & 31;
    const int wid  = threadIdx.x >> 5;
    const int b    = blockIdx.z;
    const int colbase = blockIdx.x * WCOLS;
    const int row0 = (blockIdx.y * WARPS + wid) * RH;

    const size_t img = (size_t)H * W;
    const float* __restrict__ xb = x + (size_t)b * img;
    float*       __restrict__ ob = out + (size_t)b * img;

    // effective 3x3 weights
    const float d = den[0];
    const float kv[3] = {d, 1.0f, d};
    float k[9];
    #pragma unroll
    for (int i = 0; i < 3; i++)
        #pragma unroll
        for (int j = 0; j < 3; j++)
            k[i * 3 + j] = __ldg(&w[i * 3 + j]) * kv[i] * kv[j];

    const bool leftOK  = colbase > 0;
    const bool rightOK = (colbase + WCOLS) < W;
    const float* pcol   = xb + colbase + 4 * lane;  // this lane's float4 column
    const float* pleft  = xb + colbase - 1;         // lane 0 scalar
    const float* pright = xb + colbase + WCOLS;     // lane 31 scalar

    float* ro = ob + (size_t)row0 * W + colbase + 4 * lane;

    const bool interior = (row0 > 0) && (row0 + RH < H);

    if (interior) {
        // ---------- fast path: unconditional loads, 4-deep queue ----------
        float4 q[4];
        float  eq[4];

        // issue row j (gy = row0-1+j) into queue slot (compile-time after unroll)
        auto issue = [&](int j, int slot) {
            const size_t off = (size_t)(row0 - 1 + j) * W;
            q[slot] = *reinterpret_cast<const float4*>(pcol + off);
            float e = 0.0f;
            if (lane == 0  && leftOK)  e = __ldg(pleft  + off);
            if (lane == 31 && rightOK) e = __ldg(pright + off);
            eq[slot] = e;
        };
        // expand queued row into 6-wide halo window
        auto expand = [&](int slot, float* s) {
            const float4 v = q[slot];
            float lf = __shfl_up_sync(0xffffffffu, v.w, 1);
            float rt = __shfl_down_sync(0xffffffffu, v.x, 1);
            if (lane == 0)  lf = eq[slot];
            if (lane == 31) rt = eq[slot];
            s[0] = lf; s[1] = v.x; s[2] = v.y; s[3] = v.z; s[4] = v.w; s[5] = rt;
        };

        issue(0, 0); issue(1, 1); issue(2, 2); issue(3, 3);

        float s0[6], s1[6], s2[6];
        expand(0, s0);
        expand(1, s1);

        #pragma unroll
        for (int rr = 0; rr < RH; rr++) {
            const int j = rr + 4;                 // next row to fetch (j <= 17)
            if (j <= RH + 1) issue(j, j & 3);

            expand((rr + 2) & 3, s2);

            float a0 = 0.f, a1 = 0.f, a2 = 0.f, a3 = 0.f;
            #pragma unroll
            for (int i = 0; i < 3; i++) {
                const float* s = (i == 0) ? s0 : (i == 1) ? s1 : s2;
                const float w0 = k[3 * i], w1 = k[3 * i + 1], w2 = k[3 * i + 2];
                a0 = fmaf(w0, s[0], fmaf(w1, s[1], fmaf(w2, s[2], a0)));
                a1 = fmaf(w0, s[1], fmaf(w1, s[2], fmaf(w2, s[3], a1)));
                a2 = fmaf(w0, s[2], fmaf(w1, s[3], fmaf(w2, s[4], a2)));
                a3 = fmaf(w0, s[3], fmaf(w1, s[4], fmaf(w2, s[5], a3)));
            }
            *reinterpret_cast<float4*>(ro) = make_float4(a0, a1, a2, a3);
            ro += W;

            #pragma unroll
            for (int i = 0; i < 6; i++) { s0[i] = s1[i]; s1[i] = s2[i]; }
        }
    } else {
        // ---------- edge path: first/last strip only (branchy, rare) ----------
        float r0[6], r1[6], r2[6];
        auto load_row = [&](int gy, float* s) {
            if ((unsigned)gy < (unsigned)H) {
                const size_t off = (size_t)gy * W;
                const float4 v = *reinterpret_cast<const float4*>(pcol + off);
                float lf = __shfl_up_sync(0xffffffffu, v.w, 1);
                float rt = __shfl_down_sync(0xffffffffu, v.x, 1);
                if (lane == 0)  lf = leftOK  ? __ldg(pleft  + off) : 0.0f;
                if (lane == 31) rt = rightOK ? __ldg(pright + off) : 0.0f;
                s[0] = lf; s[1] = v.x; s[2] = v.y; s[3] = v.z; s[4] = v.w; s[5] = rt;
            } else {
                #pragma unroll
                for (int i = 0; i < 6; i++) s[i] = 0.0f;
            }
        };

        load_row(row0 - 1, r0);
        load_row(row0,     r1);

        #pragma unroll
        for (int rr = 0; rr < RH; rr++) {
            load_row(row0 + rr + 1, r2);

            float a0 = 0.f, a1 = 0.f, a2 = 0.f, a3 = 0.f;
            #pragma unroll
            for (int i = 0; i < 3; i++) {
                const float* s = (i == 0) ? r0 : (i == 1) ? r1 : r2;
                const float w0 = k[3 * i], w1 = k[3 * i + 1], w2 = k[3 * i + 2];
                a0 = fmaf(w0, s[0], fmaf(w1, s[1], fmaf(w2, s[2], a0)));
                a1 = fmaf(w0, s[1], fmaf(w1, s[2], fmaf(w2, s[3], a1)));
                a2 = fmaf(w0, s[2], fmaf(w1, s[3], fmaf(w2, s[4], a2)));
                a3 = fmaf(w0, s[3], fmaf(w1, s[4], fmaf(w2, s[5], a3)));
            }
            *reinterpret_cast<float4*>(ro) = make_float4(a0, a1, a2, a3);
            ro += W;

            #pragma unroll
            for (int i = 0; i < 6; i++) { r0[i] = r1[i]; r1[i] = r2[i]; }
        }
    }
}

extern "C" void kernel_launch(void* const* d_in, const int* in_sizes, int n_in,
                              void* d_out, int out_size)
{
    const float* x   = (const float*)d_in[0];   // (16,1,2048,2048) fp32
    const float* w   = (const float*)d_in[1];   // (1,1,3,3) fp32
    const float* den = (const float*)d_in[2];   // (1,) fp32
    float* out = (float*)d_out;

    const int B = 16, H = 2048, W = 2048;
    (void)in_sizes; (void)n_in; (void)out_size;

    dim3 grid(W / WCOLS, H / (WARPS * RH), B);  // 16 x 16 x 16 = 4096 CTAs
    dim3 block(256);
    conv3x3_pf<<<grid, block>>>(x, w, den, out, H, W);
}

// round 4
// speedup vs baseline: 1.3197x; 1.2364x over previous
#include <cuda_runtime.h>
#include <cstdint>

// 3x3 stride-1 pad-1 conv, 1 channel, weight = w * outer(kx,kx), kx=[den,1,den].
// x: (16,1,2048,2048) fp32 -> out same shape.
// cp.async (LDGSTS) tile loads into smem: fire-and-forget gives huge MLP with
// zero register cost; zfill handles all halo/out-of-bounds without branches.

#define TCOLS 128            // output cols per CTA
#define TROWS 32             // output rows per CTA
#define PITCH 136            // smem row pitch in floats (4 + 128 + 4)
#define SROWS 34             // smem rows (TROWS + 2)
#define NCHUNK (SROWS * 34)  // float4 chunks per tile (34 per row)

__global__ __launch_bounds__(256)
void conv3x3_cpasync(const float* __restrict__ x,
                     const float* __restrict__ w,
                     const float* __restrict__ den,
                     float* __restrict__ out,
                     int H, int W)
{
    __shared__ float tile[SROWS * PITCH];

    const int tid  = threadIdx.x;
    const int lane = tid & 31;
    const int wid  = tid >> 5;

    const int colbase = blockIdx.x * TCOLS;
    const int row0    = blockIdx.y * TROWS;
    const int b       = blockIdx.z;

    const size_t img = (size_t)H * W;
    const float* __restrict__ xb = x + (size_t)b * img;
    float*       __restrict__ ob = out + (size_t)b * img;

    // ---------------- async tile load: 34 rows x 34 float4 chunks ----------------
    // smem float f of row r  <->  gmem (row0-1+r, colbase-4+f)
    {
        const uint32_t sbase = (uint32_t)__cvta_generic_to_shared(tile);
        #pragma unroll
        for (int c2 = tid; c2 < NCHUNK; c2 += 256) {
            const int r  = c2 / 34;
            const int cc = c2 - r * 34;
            const int gy = row0 - 1 + r;
            const int gx = colbase - 4 + 4 * cc;
            const bool valid = ((unsigned)gy < (unsigned)H) & ((unsigned)gx < (unsigned)W);
            const int off = valid ? (gy * W + gx) : 0;      // clamp ptr when zfilled
            const int srcsize = valid ? 16 : 0;
            const uint32_t daddr = sbase + (uint32_t)(r * PITCH + 4 * cc) * 4u;
            asm volatile("cp.async.cg.shared.global [%0], [%1], 16, %2;"
                         :: "r"(daddr), "l"(xb + off), "r"(srcsize));
        }
        asm volatile("cp.async.commit_group;");
    }

    // effective 3x3 weights (overlaps with loads in flight)
    const float d = den[0];
    const float kv[3] = {d, 1.0f, d};
    float k[9];
    #pragma unroll
    for (int i = 0; i < 3; i++)
        #pragma unroll
        for (int j = 0; j < 3; j++)
            k[i * 3 + j] = __ldg(&w[i * 3 + j]) * kv[i] * kv[j];

    asm volatile("cp.async.wait_group 0;");
    __syncthreads();

    // ---------------- compute: warp w -> output rows [4w, 4w+4) ----------------
    // window for lane: smem floats [3+4*lane .. 8+4*lane] of each row
    const int base_f = 4 * lane;
    auto ldrow = [&](int r, float* s) {
        const float* p = &tile[r * PITCH + base_f];
        const float4 v = *reinterpret_cast<const float4*>(p + 4);
        s[0] = p[3]; s[1] = v.x; s[2] = v.y; s[3] = v.z; s[4] = v.w; s[5] = p[8];
    };

    float s0[6], s1[6], s2[6];
    const int lr0 = 4 * wid;        // local smem row of first needed input row
    ldrow(lr0,     s0);
    ldrow(lr0 + 1, s1);

    float* ro = ob + (size_t)(row0 + 4 * wid) * W + colbase + 4 * lane;

    #pragma unroll
    for (int oo = 0; oo < 4; oo++) {
        ldrow(lr0 + 2 + oo, s2);

        float a0 = 0.f, a1 = 0.f, a2 = 0.f, a3 = 0.f;
        #pragma unroll
        for (int i = 0; i < 3; i++) {
            const float* s = (i == 0) ? s0 : (i == 1) ? s1 : s2;
            const float w0 = k[3 * i], w1 = k[3 * i + 1], w2 = k[3 * i + 2];
            a0 = fmaf(w0, s[0], fmaf(w1, s[1], fmaf(w2, s[2], a0)));
            a1 = fmaf(w0, s[1], fmaf(w1, s[2], fmaf(w2, s[3], a1)));
            a2 = fmaf(w0, s[2], fmaf(w1, s[3], fmaf(w2, s[4], a2)));
            a3 = fmaf(w0, s[3], fmaf(w1, s[4], fmaf(w2, s[5], a3)));
        }
        *reinterpret_cast<float4*>(ro) = make_float4(a0, a1, a2, a3);
        ro += W;

        #pragma unroll
        for (int i = 0; i < 6; i++) { s0[i] = s1[i]; s1[i] = s2[i]; }
    }
}

extern "C" void kernel_launch(void* const* d_in, const int* in_sizes, int n_in,
                              void* d_out, int out_size)
{
    const float* x   = (const float*)d_in[0];   // (16,1,2048,2048) fp32
    const float* w   = (const float*)d_in[1];   // (1,1,3,3) fp32
    const float* den = (const float*)d_in[2];   // (1,) fp32
    float* out = (float*)d_out;

    const int B = 16, H = 2048, W = 2048;
    (void)in_sizes; (void)n_in; (void)out_size;

    dim3 grid(W / TCOLS, H / TROWS, B);   // 16 x 64 x 16 = 16384 CTAs
    dim3 block(256);
    conv3x3_cpasync<<<grid, block>>>(x, w, den, out, H, W);
}